// round 14
// baseline (speedup 1.0000x reference)
#include <cuda_runtime.h>
#include <cuda_fp16.h>
#include <math.h>
#include <stdint.h>

// QuantumTransformerBlock — closed-form quantum ops + fp16 tensor-core FFN, f-split warp pairs.
// R14: software-pipelined table LDS (prefetch i+1 before MMAs of i), pointer-increment
// addressing, h stashed in smem to stay under the 64-reg cap.
// Loop: warp pair shares 2 tiles, each warp half the f-range; GEMM1 mma.m16n8k8.f16
// (f16 D/C, bias in C, relu = max.f16x2, D feeds GEMM2 A directly);
// GEMM2 chunk-paired mma.m16n8k16 fp32 acc. Pack kernel prebuilds fragment tables.

#define TPB   1024
#define GRID  148
#define NTASKS 2048
#define PAIRS_PER_BLOCK 14     // 148*14 = 2072 >= 2048

// smem layout (floats)
#define WB_OFF   0        // 16384 u32 as uint4[4096]: [128 cp][32 lane] (w1c0,w1c1,w2c0,w2c1)
#define B16_OFF  16384    // 1024 u32 as uint2[512]: [128 cp][4 t] (bias f16x2 c0, c1)
#define SZ_OFF   17408    // 8192 floats: [32 warp][32 tok][8 j]  z, later partial-sum exchange
#define H_OFF    25600    // 4096 floats: [16 pair][32 tok][8 j]  h stash (persists over loop)
#define SMEM_FLOATS (H_OFF + 16 * 256)
#define SMEM_BYTES (SMEM_FLOATS * 4)       // 118784

__device__ uint4 g_wb[4096];
__device__ uint2 g_b16[512];

__device__ __forceinline__ uint32_t pack_f16x2(float lo, float hi) {
    uint32_t d; asm("cvt.rn.f16x2.f32 %0, %1, %2;" : "=r"(d) : "f"(hi), "f"(lo)); return d;
}
__device__ __forceinline__ uint32_t hmax2z(uint32_t a) {
    uint32_t d; asm("max.f16x2 %0, %1, %2;" : "=r"(d) : "r"(a), "r"(0u)); return d;
}

#define MMA8_H(D0,D1, A0,A1, B0, C0,C1) \
  asm("mma.sync.aligned.m16n8k8.row.col.f16.f16.f16.f16 " \
      "{%0,%1}, {%2,%3}, {%4}, {%5,%6};" \
      : "=r"(D0),"=r"(D1) : "r"(A0),"r"(A1), "r"(B0), "r"(C0),"r"(C1))

#define MMA16_F32(D0,D1,D2,D3, A0,A1,A2,A3, B0,B1, C0,C1,C2,C3) \
  asm("mma.sync.aligned.m16n8k16.row.col.f32.f16.f16.f32 " \
      "{%0,%1,%2,%3}, {%4,%5,%6,%7}, {%8,%9}, {%10,%11,%12,%13};" \
      : "=f"(D0),"=f"(D1),"=f"(D2),"=f"(D3) \
      : "r"(A0),"r"(A1),"r"(A2),"r"(A3), "r"(B0),"r"(B1), \
        "f"(C0),"f"(C1),"f"(C2),"f"(C3))

// ---------- pack kernel: build fused mma-fragment tables once ----------
__global__ void qtb_pack(const float* __restrict__ W1, const float* __restrict__ b1,
                         const float* __restrict__ W2)
{
    int i = blockIdx.x * 256 + threadIdx.x;        // [0, 4096)
    {
        int cp = i >> 5, lane_ = i & 31;
        int gq = lane_ >> 2, tq = lane_ & 3;
        int c0 = cp * 2, c1 = c0 + 1;
        int f0 = c0 * 8 + gq, f1 = c1 * 8 + gq;
        uint4 v;
        v.x = pack_f16x2(W1[f0 * 8 + 2 * tq], W1[f0 * 8 + 2 * tq + 1]);
        v.y = pack_f16x2(W1[f1 * 8 + 2 * tq], W1[f1 * 8 + 2 * tq + 1]);
        v.z = pack_f16x2(W2[gq * 2048 + c0 * 8 + 2 * tq], W2[gq * 2048 + c0 * 8 + 2 * tq + 1]);
        v.w = pack_f16x2(W2[gq * 2048 + c1 * 8 + 2 * tq], W2[gq * 2048 + c1 * 8 + 2 * tq + 1]);
        g_wb[i] = v;
    }
    if (i < 512) {
        int cp = i >> 2, tq = i & 3;
        int c0 = cp * 2, c1 = c0 + 1;
        uint2 v;
        v.x = pack_f16x2(b1[c0 * 8 + 2 * tq], b1[c0 * 8 + 2 * tq + 1]);
        v.y = pack_f16x2(b1[c1 * 8 + 2 * tq], b1[c1 * 8 + 2 * tq + 1]);
        g_b16[i] = v;
    }
}

// ---------- main kernel ----------
__global__ void __launch_bounds__(TPB, 1) qtb_kernel(
    const float* __restrict__ x, const float* __restrict__ theta, const float* __restrict__ phi,
    const float* __restrict__ b2,
    const float* __restrict__ g1, const float* __restrict__ be1,
    const float* __restrict__ g2, const float* __restrict__ be2,
    float* __restrict__ out)
{
    extern __shared__ float smem[];
    const int tid = threadIdx.x;
    uint4* pWB  = (uint4*)(smem + WB_OFF);
    uint2* pB16 = (uint2*)(smem + B16_OFF);

    // preamble: coalesced copy of prepacked tables (L2-hot)
    #pragma unroll
    for (int k = 0; k < 4; k++) pWB[tid + k * TPB] = g_wb[tid + k * TPB];
    if (tid < 512) pB16[tid] = g_b16[tid];

    const int wid  = tid >> 5, lane = tid & 31;
    const int g    = lane >> 2, t = lane & 3;
    const int pair = wid >> 1, half = wid & 1;

    const int task = blockIdx.x * PAIRS_PER_BLOCK + pair;
    const bool act = (pair < PAIRS_PER_BLOCK) && (task < NTASKS);
    const int taskc = act ? task : 0;
    const int tok  = taskc * 32 + lane;            // one token per lane

    // ---- front: closed-form attn + LN1 + ffn_quantum (fast __cosf) ----
    {
        float th_[8], cph[8], gg_[8], bb_[8];
        #pragma unroll
        for (int j = 0; j < 8; j++) {
            th_[j] = __ldg(theta + j);
            cph[j] = __cosf(__ldg(phi + j));
            gg_[j] = __ldg(g1 + j);
            bb_[j] = __ldg(be1 + j);
        }
        const float* xp = x + (size_t)tok * 8;
        float4 a4 = __ldg((const float4*)xp);
        float4 b4 = __ldg((const float4*)(xp + 4));
        float xv[8] = {a4.x, a4.y, a4.z, a4.w, b4.x, b4.y, b4.z, b4.w};

        float c_[8];
        #pragma unroll
        for (int j = 0; j < 8; j++) c_[j] = __cosf(xv[j] + th_[j]);
        float attn[8];
        float pr = c_[0];
        #pragma unroll
        for (int j = 1; j < 8; j++) { pr *= c_[j]; attn[j] = pr; }
        float qr = c_[1];
        #pragma unroll
        for (int j = 2; j < 8; j++) qr *= c_[j];
        attn[0] = qr;

        float y[8]; float s = 0.f;
        #pragma unroll
        for (int j = 0; j < 8; j++) { y[j] = xv[j] + attn[j]; s += y[j]; }
        float m = s * 0.125f, v = 0.f;
        #pragma unroll
        for (int j = 0; j < 8; j++) { float d = y[j] - m; v += d * d; }
        float inv = rsqrtf(v * 0.125f + 1e-5f);

        float* sz = smem + SZ_OFF + wid * 256 + lane * 8;
        float* sh = smem + H_OFF + pair * 256 + lane * 8;
        #pragma unroll
        for (int j = 0; j < 8; j++) {
            float hj = (y[j] - m) * inv * gg_[j] + bb_[j];
            if (half == 0) sh[j] = hj;             // stash h (epilogue reads own lane)
            sz[j] = cph[j] * __cosf(hj);           // z (per-warp private copy)
        }
    }
    __syncthreads();                                // tables + z ready

    // ---- A-frags: tile0 = rows 0-15, tile1 = rows 16-31 ----
    const float* z0 = smem + SZ_OFF + wid * 256;
    uint32_t A0g, A0G, A1g, A1G;
    {
        int i0 = g * 8 + 2 * t;
        A0g = pack_f16x2(z0[i0],       z0[i0 + 1]);
        A0G = pack_f16x2(z0[i0 + 64],  z0[i0 + 65]);
        A1g = pack_f16x2(z0[i0 + 128], z0[i0 + 129]);
        A1G = pack_f16x2(z0[i0 + 192], z0[i0 + 193]);
    }

    // ---- loop: this warp's 64 chunk-pairs, software-pipelined LDS ----
    float acc0[4] = {0,0,0,0};
    float acc1[4] = {0,0,0,0};
    const int cpbase = half << 6;
    const uint4* wp = pWB + (cpbase << 5) + lane;
    const uint2* bp = pB16 + (cpbase << 2) + t;

    uint4 wq = *wp;                                 // prologue load
    uint2 bw = *bp;

    #pragma unroll 4
    for (int i = 0; i < 64; i++) {
        wp += 32; bp += 4;
        uint4 nwq = *wp;                            // prefetch i+1 (one-past-end lands in
        uint2 nbw = *bp;                            //  adjacent smem, never consumed)

        uint32_t d00, d01, d10, d11;
        MMA8_H(d00, d01, A0g, A0G, wq.x, bw.x, bw.x);
        MMA8_H(d10, d11, A0g, A0G, wq.y, bw.y, bw.y);
        uint32_t e00, e01, e10, e11;
        MMA8_H(e00, e01, A1g, A1G, wq.x, bw.x, bw.x);
        MMA8_H(e10, e11, A1g, A1G, wq.y, bw.y, bw.y);

        d00 = hmax2z(d00); d01 = hmax2z(d01); d10 = hmax2z(d10); d11 = hmax2z(d11);
        MMA16_F32(acc0[0],acc0[1],acc0[2],acc0[3],
                  d00,d01,d10,d11, wq.z,wq.w,
                  acc0[0],acc0[1],acc0[2],acc0[3]);

        e00 = hmax2z(e00); e01 = hmax2z(e01); e10 = hmax2z(e10); e11 = hmax2z(e11);
        MMA16_F32(acc1[0],acc1[1],acc1[2],acc1[3],
                  e00,e01,e10,e11, wq.z,wq.w,
                  acc1[0],acc1[1],acc1[2],acc1[3]);

        wq = nwq; bw = nbw;
    }

    // ---- exchange partial sums between the two f-halves ----
    __syncthreads();
    float* sE = smem + SZ_OFF + wid * 256;
    sE[(g)*8      + 2*t]     = acc0[0];
    sE[(g)*8      + 2*t + 1] = acc0[1];
    sE[(g+8)*8    + 2*t]     = acc0[2];
    sE[(g+8)*8    + 2*t + 1] = acc0[3];
    sE[(16+g)*8   + 2*t]     = acc1[0];
    sE[(16+g)*8   + 2*t + 1] = acc1[1];
    sE[(24+g)*8   + 2*t]     = acc1[2];
    sE[(24+g)*8   + 2*t + 1] = acc1[3];
    __syncthreads();

    // ---- epilogue (half-0 warps): residual + b2 + LN2 ----
    if (act && half == 0) {
        const float* sh   = smem + H_OFF + pair * 256 + lane * 8;
        const float* sOwn = smem + SZ_OFF + wid * 256       + lane * 8;
        const float* sPar = smem + SZ_OFF + (wid ^ 1) * 256 + lane * 8;
        float w[8]; float s2 = 0.f;
        #pragma unroll
        for (int e = 0; e < 8; e++) {
            w[e] = sh[e] + sOwn[e] + sPar[e] + __ldg(b2 + e);
            s2 += w[e];
        }
        float m2 = s2 * 0.125f, v2 = 0.f;
        #pragma unroll
        for (int e = 0; e < 8; e++) { float d = w[e] - m2; v2 += d * d; }
        float inv2 = rsqrtf(v2 * 0.125f + 1e-5f);
        float o[8];
        #pragma unroll
        for (int e = 0; e < 8; e++)
            o[e] = (w[e] - m2) * inv2 * __ldg(g2 + e) + __ldg(be2 + e);
        float* op = out + (size_t)tok * 8;
        *(float4*)op       = make_float4(o[0], o[1], o[2], o[3]);
        *(float4*)(op + 4) = make_float4(o[4], o[5], o[6], o[7]);
    }
}

extern "C" void kernel_launch(void* const* d_in, const int* in_sizes, int n_in,
                              void* d_out, int out_size) {
    const float* x      = (const float*)d_in[0];
    const float* theta  = (const float*)d_in[1];
    const float* phi    = (const float*)d_in[2];
    const float* W1     = (const float*)d_in[3];
    const float* b1     = (const float*)d_in[4];
    const float* W2     = (const float*)d_in[5];
    const float* b2     = (const float*)d_in[6];
    const float* gamma1 = (const float*)d_in[7];
    const float* beta1  = (const float*)d_in[8];
    const float* gamma2 = (const float*)d_in[9];
    const float* beta2  = (const float*)d_in[10];
    float* out = (float*)d_out;

    qtb_pack<<<16, 256>>>(W1, b1, W2);
    cudaFuncSetAttribute(qtb_kernel, cudaFuncAttributeMaxDynamicSharedMemorySize, SMEM_BYTES);
    qtb_kernel<<<GRID, TPB, SMEM_BYTES>>>(x, theta, phi, b2,
                                          gamma1, beta1, gamma2, beta2, out);
}

// round 15
// speedup vs baseline: 1.0226x; 1.0226x over previous
#include <cuda_runtime.h>
#include <cuda_fp16.h>
#include <math.h>
#include <stdint.h>

// QuantumTransformerBlock — closed-form quantum ops + fp16 tensor-core FFN, f-split warp pairs.
// R15 = R13 (best) + two pressure-reducing deltas only:
//   (1) h[8] stashed in smem across the loop (frees 8 regs at the 64-reg cap)
//   (2) pointer-bump table addressing (fewer IMADs), NO prefetch double-buffer.
// Loop: warp pair shares 2 tiles, each warp half the f-range; GEMM1 mma.m16n8k8.f16
// (f16 D/C, bias in C, relu = max.f16x2, D feeds GEMM2 A directly);
// GEMM2 chunk-paired mma.m16n8k16 fp32 acc. Pack kernel prebuilds fragment tables.

#define TPB   1024
#define GRID  148
#define NTASKS 2048
#define PAIRS_PER_BLOCK 14     // 148*14 = 2072 >= 2048

// smem layout (floats)
#define WB_OFF   0        // 16384 u32 as uint4[4096]: [128 cp][32 lane] (w1c0,w1c1,w2c0,w2c1)
#define B16_OFF  16384    // 1024 u32 as uint2[512]: [128 cp][4 t] (bias f16x2 c0, c1)
#define SZ_OFF   17408    // 8192 floats: [32 warp][32 tok][8 j]  z, later partial-sum exchange
#define H_OFF    25600    // 4096 floats: [16 pair][32 tok][8 j]  h stash (persists over loop)
#define SMEM_FLOATS (H_OFF + 16 * 256)
#define SMEM_BYTES (SMEM_FLOATS * 4)       // 118784

__device__ uint4 g_wb[4096];
__device__ uint2 g_b16[512];

__device__ __forceinline__ uint32_t pack_f16x2(float lo, float hi) {
    uint32_t d; asm("cvt.rn.f16x2.f32 %0, %1, %2;" : "=r"(d) : "f"(hi), "f"(lo)); return d;
}
__device__ __forceinline__ uint32_t hmax2z(uint32_t a) {
    uint32_t d; asm("max.f16x2 %0, %1, %2;" : "=r"(d) : "r"(a), "r"(0u)); return d;
}

#define MMA8_H(D0,D1, A0,A1, B0, C0,C1) \
  asm("mma.sync.aligned.m16n8k8.row.col.f16.f16.f16.f16 " \
      "{%0,%1}, {%2,%3}, {%4}, {%5,%6};" \
      : "=r"(D0),"=r"(D1) : "r"(A0),"r"(A1), "r"(B0), "r"(C0),"r"(C1))

#define MMA16_F32(D0,D1,D2,D3, A0,A1,A2,A3, B0,B1, C0,C1,C2,C3) \
  asm("mma.sync.aligned.m16n8k16.row.col.f32.f16.f16.f32 " \
      "{%0,%1,%2,%3}, {%4,%5,%6,%7}, {%8,%9}, {%10,%11,%12,%13};" \
      : "=f"(D0),"=f"(D1),"=f"(D2),"=f"(D3) \
      : "r"(A0),"r"(A1),"r"(A2),"r"(A3), "r"(B0),"r"(B1), \
        "f"(C0),"f"(C1),"f"(C2),"f"(C3))

// ---------- pack kernel: build fused mma-fragment tables once ----------
__global__ void qtb_pack(const float* __restrict__ W1, const float* __restrict__ b1,
                         const float* __restrict__ W2)
{
    int i = blockIdx.x * 256 + threadIdx.x;        // [0, 4096)
    {
        int cp = i >> 5, lane_ = i & 31;
        int gq = lane_ >> 2, tq = lane_ & 3;
        int c0 = cp * 2, c1 = c0 + 1;
        int f0 = c0 * 8 + gq, f1 = c1 * 8 + gq;
        uint4 v;
        v.x = pack_f16x2(W1[f0 * 8 + 2 * tq], W1[f0 * 8 + 2 * tq + 1]);
        v.y = pack_f16x2(W1[f1 * 8 + 2 * tq], W1[f1 * 8 + 2 * tq + 1]);
        v.z = pack_f16x2(W2[gq * 2048 + c0 * 8 + 2 * tq], W2[gq * 2048 + c0 * 8 + 2 * tq + 1]);
        v.w = pack_f16x2(W2[gq * 2048 + c1 * 8 + 2 * tq], W2[gq * 2048 + c1 * 8 + 2 * tq + 1]);
        g_wb[i] = v;
    }
    if (i < 512) {
        int cp = i >> 2, tq = i & 3;
        int c0 = cp * 2, c1 = c0 + 1;
        uint2 v;
        v.x = pack_f16x2(b1[c0 * 8 + 2 * tq], b1[c0 * 8 + 2 * tq + 1]);
        v.y = pack_f16x2(b1[c1 * 8 + 2 * tq], b1[c1 * 8 + 2 * tq + 1]);
        g_b16[i] = v;
    }
}

// ---------- main kernel ----------
__global__ void __launch_bounds__(TPB, 1) qtb_kernel(
    const float* __restrict__ x, const float* __restrict__ theta, const float* __restrict__ phi,
    const float* __restrict__ b2,
    const float* __restrict__ g1, const float* __restrict__ be1,
    const float* __restrict__ g2, const float* __restrict__ be2,
    float* __restrict__ out)
{
    extern __shared__ float smem[];
    const int tid = threadIdx.x;
    uint4* pWB  = (uint4*)(smem + WB_OFF);
    uint2* pB16 = (uint2*)(smem + B16_OFF);

    // preamble: coalesced copy of prepacked tables (L2-hot)
    #pragma unroll
    for (int k = 0; k < 4; k++) pWB[tid + k * TPB] = g_wb[tid + k * TPB];
    if (tid < 512) pB16[tid] = g_b16[tid];

    const int wid  = tid >> 5, lane = tid & 31;
    const int g    = lane >> 2, t = lane & 3;
    const int pair = wid >> 1, half = wid & 1;

    const int task = blockIdx.x * PAIRS_PER_BLOCK + pair;
    const bool act = (pair < PAIRS_PER_BLOCK) && (task < NTASKS);
    const int taskc = act ? task : 0;
    const int tok  = taskc * 32 + lane;            // one token per lane

    // ---- front: closed-form attn + LN1 + ffn_quantum (fast __cosf) ----
    {
        float th_[8], cph[8], gg_[8], bb_[8];
        #pragma unroll
        for (int j = 0; j < 8; j++) {
            th_[j] = __ldg(theta + j);
            cph[j] = __cosf(__ldg(phi + j));
            gg_[j] = __ldg(g1 + j);
            bb_[j] = __ldg(be1 + j);
        }
        const float* xp = x + (size_t)tok * 8;
        float4 a4 = __ldg((const float4*)xp);
        float4 b4 = __ldg((const float4*)(xp + 4));
        float xv[8] = {a4.x, a4.y, a4.z, a4.w, b4.x, b4.y, b4.z, b4.w};

        float c_[8];
        #pragma unroll
        for (int j = 0; j < 8; j++) c_[j] = __cosf(xv[j] + th_[j]);
        float attn[8];
        float pr = c_[0];
        #pragma unroll
        for (int j = 1; j < 8; j++) { pr *= c_[j]; attn[j] = pr; }
        float qr = c_[1];
        #pragma unroll
        for (int j = 2; j < 8; j++) qr *= c_[j];
        attn[0] = qr;

        float y[8]; float s = 0.f;
        #pragma unroll
        for (int j = 0; j < 8; j++) { y[j] = xv[j] + attn[j]; s += y[j]; }
        float m = s * 0.125f, v = 0.f;
        #pragma unroll
        for (int j = 0; j < 8; j++) { float d = y[j] - m; v += d * d; }
        float inv = rsqrtf(v * 0.125f + 1e-5f);

        float* sz = smem + SZ_OFF + wid * 256 + lane * 8;
        float* sh = smem + H_OFF + pair * 256 + lane * 8;
        #pragma unroll
        for (int j = 0; j < 8; j++) {
            float hj = (y[j] - m) * inv * gg_[j] + bb_[j];
            if (half == 0) sh[j] = hj;             // stash h (epilogue reads own lane back)
            sz[j] = cph[j] * __cosf(hj);           // z (per-warp private copy)
        }
    }
    __syncthreads();                                // tables + z ready

    // ---- A-frags: tile0 = rows 0-15, tile1 = rows 16-31 ----
    const float* z0 = smem + SZ_OFF + wid * 256;
    uint32_t A0g, A0G, A1g, A1G;
    {
        int i0 = g * 8 + 2 * t;
        A0g = pack_f16x2(z0[i0],       z0[i0 + 1]);
        A0G = pack_f16x2(z0[i0 + 64],  z0[i0 + 65]);
        A1g = pack_f16x2(z0[i0 + 128], z0[i0 + 129]);
        A1G = pack_f16x2(z0[i0 + 192], z0[i0 + 193]);
    }

    // ---- loop: this warp's 64 chunk-pairs (half of f), pointer-bump addressing ----
    float acc0[4] = {0,0,0,0};
    float acc1[4] = {0,0,0,0};
    const int cpbase = half << 6;
    const uint4* wp = pWB + (cpbase << 5) + lane;
    const uint2* bp = pB16 + (cpbase << 2) + t;

    #pragma unroll 4
    for (int i = 0; i < 64; i++) {
        uint4 wq = *wp; wp += 32;
        uint2 bw = *bp; bp += 4;

        uint32_t d00, d01, d10, d11;
        MMA8_H(d00, d01, A0g, A0G, wq.x, bw.x, bw.x);
        MMA8_H(d10, d11, A0g, A0G, wq.y, bw.y, bw.y);
        d00 = hmax2z(d00); d01 = hmax2z(d01); d10 = hmax2z(d10); d11 = hmax2z(d11);
        MMA16_F32(acc0[0],acc0[1],acc0[2],acc0[3],
                  d00,d01,d10,d11, wq.z,wq.w,
                  acc0[0],acc0[1],acc0[2],acc0[3]);

        MMA8_H(d00, d01, A1g, A1G, wq.x, bw.x, bw.x);
        MMA8_H(d10, d11, A1g, A1G, wq.y, bw.y, bw.y);
        d00 = hmax2z(d00); d01 = hmax2z(d01); d10 = hmax2z(d10); d11 = hmax2z(d11);
        MMA16_F32(acc1[0],acc1[1],acc1[2],acc1[3],
                  d00,d01,d10,d11, wq.z,wq.w,
                  acc1[0],acc1[1],acc1[2],acc1[3]);
    }

    // ---- exchange partial sums between the two f-halves ----
    __syncthreads();
    float* sE = smem + SZ_OFF + wid * 256;
    sE[(g)*8      + 2*t]     = acc0[0];
    sE[(g)*8      + 2*t + 1] = acc0[1];
    sE[(g+8)*8    + 2*t]     = acc0[2];
    sE[(g+8)*8    + 2*t + 1] = acc0[3];
    sE[(16+g)*8   + 2*t]     = acc1[0];
    sE[(16+g)*8   + 2*t + 1] = acc1[1];
    sE[(24+g)*8   + 2*t]     = acc1[2];
    sE[(24+g)*8   + 2*t + 1] = acc1[3];
    __syncthreads();

    // ---- epilogue (half-0 warps): residual + b2 + LN2 ----
    if (act && half == 0) {
        const float* sh   = smem + H_OFF + pair * 256 + lane * 8;
        const float* sOwn = smem + SZ_OFF + wid * 256       + lane * 8;
        const float* sPar = smem + SZ_OFF + (wid ^ 1) * 256 + lane * 8;
        float w[8]; float s2 = 0.f;
        #pragma unroll
        for (int e = 0; e < 8; e++) {
            w[e] = sh[e] + sOwn[e] + sPar[e] + __ldg(b2 + e);
            s2 += w[e];
        }
        float m2 = s2 * 0.125f, v2 = 0.f;
        #pragma unroll
        for (int e = 0; e < 8; e++) { float d = w[e] - m2; v2 += d * d; }
        float inv2 = rsqrtf(v2 * 0.125f + 1e-5f);
        float o[8];
        #pragma unroll
        for (int e = 0; e < 8; e++)
            o[e] = (w[e] - m2) * inv2 * __ldg(g2 + e) + __ldg(be2 + e);
        float* op = out + (size_t)tok * 8;
        *(float4*)op       = make_float4(o[0], o[1], o[2], o[3]);
        *(float4*)(op + 4) = make_float4(o[4], o[5], o[6], o[7]);
    }
}

extern "C" void kernel_launch(void* const* d_in, const int* in_sizes, int n_in,
                              void* d_out, int out_size) {
    const float* x      = (const float*)d_in[0];
    const float* theta  = (const float*)d_in[1];
    const float* phi    = (const float*)d_in[2];
    const float* W1     = (const float*)d_in[3];
    const float* b1     = (const float*)d_in[4];
    const float* W2     = (const float*)d_in[5];
    const float* b2     = (const float*)d_in[6];
    const float* gamma1 = (const float*)d_in[7];
    const float* beta1  = (const float*)d_in[8];
    const float* gamma2 = (const float*)d_in[9];
    const float* beta2  = (const float*)d_in[10];
    float* out = (float*)d_out;

    qtb_pack<<<16, 256>>>(W1, b1, W2);
    cudaFuncSetAttribute(qtb_kernel, cudaFuncAttributeMaxDynamicSharedMemorySize, SMEM_BYTES);
    qtb_kernel<<<GRID, TPB, SMEM_BYTES>>>(x, theta, phi, b2,
                                          gamma1, beta1, gamma2, beta2, out);
}

// round 16
// speedup vs baseline: 1.0361x; 1.0132x over previous
#include <cuda_runtime.h>
#include <cuda_fp16.h>
#include <math.h>
#include <stdint.h>

// QuantumTransformerBlock — closed-form quantum ops + fp16 tensor-core FFN, f-split warp pairs.
// R16 = R13 + f16-accumulate GEMM2: mma.m16n8k16.f16.f16.f16.f16 with 4-way rotating f16
// accumulators (32 steps each), summed in fp32 at the epilogue. GEMM1 unchanged:
// mma.m16n8k8.f16 (f16 D/C, bias in C, relu = max.f16x2, D feeds GEMM2 A directly).
// Pack kernel prebuilds fragment tables; main preamble is a coalesced copy.

#define TPB   1024
#define GRID  148
#define NTASKS 2048
#define PAIRS_PER_BLOCK 14     // 148*14 = 2072 >= 2048

// smem layout (floats)
#define WB_OFF   0        // 16384 u32 as uint4[4096]: [128 cp][32 lane] (w1c0,w1c1,w2c0,w2c1)
#define B16_OFF  16384    // 1024 u32 as uint2[512]: [128 cp][4 t] (bias f16x2 c0, c1)
#define SZ_OFF   17408    // 8192 floats: [32 warp][32 tok][8 j]  z, later partial-sum exchange
#define SMEM_FLOATS (SZ_OFF + 32 * 256)
#define SMEM_BYTES (SMEM_FLOATS * 4)       // 102400

__device__ uint4 g_wb[4096];
__device__ uint2 g_b16[512];

__device__ __forceinline__ uint32_t pack_f16x2(float lo, float hi) {
    uint32_t d; asm("cvt.rn.f16x2.f32 %0, %1, %2;" : "=r"(d) : "f"(hi), "f"(lo)); return d;
}
__device__ __forceinline__ uint32_t hmax2z(uint32_t a) {
    uint32_t d; asm("max.f16x2 %0, %1, %2;" : "=r"(d) : "r"(a), "r"(0u)); return d;
}
__device__ __forceinline__ float2 h2_to_f2(uint32_t u) {
    __half2 hh = *reinterpret_cast<__half2*>(&u);
    return __half22float2(hh);
}

#define MMA8_H(D0,D1, A0,A1, B0, C0,C1) \
  asm("mma.sync.aligned.m16n8k8.row.col.f16.f16.f16.f16 " \
      "{%0,%1}, {%2,%3}, {%4}, {%5,%6};" \
      : "=r"(D0),"=r"(D1) : "r"(A0),"r"(A1), "r"(B0), "r"(C0),"r"(C1))

// m16n8k16, f16 in / f16 out (D,C are 2x f16x2)
#define MMA16_H(D0,D1, A0,A1,A2,A3, B0,B1, C0,C1) \
  asm("mma.sync.aligned.m16n8k16.row.col.f16.f16.f16.f16 " \
      "{%0,%1}, {%2,%3,%4,%5}, {%6,%7}, {%8,%9};" \
      : "=r"(D0),"=r"(D1) \
      : "r"(A0),"r"(A1),"r"(A2),"r"(A3), "r"(B0),"r"(B1), "r"(C0),"r"(C1))

// ---------- pack kernel: build fused mma-fragment tables once ----------
__global__ void qtb_pack(const float* __restrict__ W1, const float* __restrict__ b1,
                         const float* __restrict__ W2)
{
    int i = blockIdx.x * 256 + threadIdx.x;        // [0, 4096)
    {
        int cp = i >> 5, lane_ = i & 31;
        int gq = lane_ >> 2, tq = lane_ & 3;
        int c0 = cp * 2, c1 = c0 + 1;
        int f0 = c0 * 8 + gq, f1 = c1 * 8 + gq;
        uint4 v;
        v.x = pack_f16x2(W1[f0 * 8 + 2 * tq], W1[f0 * 8 + 2 * tq + 1]);
        v.y = pack_f16x2(W1[f1 * 8 + 2 * tq], W1[f1 * 8 + 2 * tq + 1]);
        v.z = pack_f16x2(W2[gq * 2048 + c0 * 8 + 2 * tq], W2[gq * 2048 + c0 * 8 + 2 * tq + 1]);
        v.w = pack_f16x2(W2[gq * 2048 + c1 * 8 + 2 * tq], W2[gq * 2048 + c1 * 8 + 2 * tq + 1]);
        g_wb[i] = v;
    }
    if (i < 512) {
        int cp = i >> 2, tq = i & 3;
        int c0 = cp * 2, c1 = c0 + 1;
        uint2 v;
        v.x = pack_f16x2(b1[c0 * 8 + 2 * tq], b1[c0 * 8 + 2 * tq + 1]);
        v.y = pack_f16x2(b1[c1 * 8 + 2 * tq], b1[c1 * 8 + 2 * tq + 1]);
        g_b16[i] = v;
    }
}

// ---------- main kernel ----------
__global__ void __launch_bounds__(TPB, 1) qtb_kernel(
    const float* __restrict__ x, const float* __restrict__ theta, const float* __restrict__ phi,
    const float* __restrict__ b2,
    const float* __restrict__ g1, const float* __restrict__ be1,
    const float* __restrict__ g2, const float* __restrict__ be2,
    float* __restrict__ out)
{
    extern __shared__ float smem[];
    const int tid = threadIdx.x;
    uint4* pWB  = (uint4*)(smem + WB_OFF);
    uint2* pB16 = (uint2*)(smem + B16_OFF);

    // preamble: coalesced copy of prepacked tables (L2-hot)
    #pragma unroll
    for (int k = 0; k < 4; k++) pWB[tid + k * TPB] = g_wb[tid + k * TPB];
    if (tid < 512) pB16[tid] = g_b16[tid];

    const int wid  = tid >> 5, lane = tid & 31;
    const int g    = lane >> 2, t = lane & 3;
    const int pair = wid >> 1, half = wid & 1;

    const int task = blockIdx.x * PAIRS_PER_BLOCK + pair;
    const bool act = (pair < PAIRS_PER_BLOCK) && (task < NTASKS);
    const int taskc = act ? task : 0;
    const int tok  = taskc * 32 + lane;            // one token per lane

    // ---- front: closed-form attn + LN1 + ffn_quantum (fast __cosf) ----
    float h[8];
    {
        float th_[8], cph[8], gg_[8], bb_[8];
        #pragma unroll
        for (int j = 0; j < 8; j++) {
            th_[j] = __ldg(theta + j);
            cph[j] = __cosf(__ldg(phi + j));
            gg_[j] = __ldg(g1 + j);
            bb_[j] = __ldg(be1 + j);
        }
        const float* xp = x + (size_t)tok * 8;
        float4 a4 = __ldg((const float4*)xp);
        float4 b4 = __ldg((const float4*)(xp + 4));
        float xv[8] = {a4.x, a4.y, a4.z, a4.w, b4.x, b4.y, b4.z, b4.w};

        float c_[8];
        #pragma unroll
        for (int j = 0; j < 8; j++) c_[j] = __cosf(xv[j] + th_[j]);
        float attn[8];
        float pr = c_[0];
        #pragma unroll
        for (int j = 1; j < 8; j++) { pr *= c_[j]; attn[j] = pr; }
        float qr = c_[1];
        #pragma unroll
        for (int j = 2; j < 8; j++) qr *= c_[j];
        attn[0] = qr;

        float y[8]; float s = 0.f;
        #pragma unroll
        for (int j = 0; j < 8; j++) { y[j] = xv[j] + attn[j]; s += y[j]; }
        float m = s * 0.125f, v = 0.f;
        #pragma unroll
        for (int j = 0; j < 8; j++) { float d = y[j] - m; v += d * d; }
        float inv = rsqrtf(v * 0.125f + 1e-5f);

        float* sz = smem + SZ_OFF + wid * 256 + lane * 8;
        #pragma unroll
        for (int j = 0; j < 8; j++) {
            h[j] = (y[j] - m) * inv * gg_[j] + bb_[j];
            sz[j] = cph[j] * __cosf(h[j]);         // z (per-warp private copy)
        }
    }
    __syncthreads();                                // tables + z ready

    // ---- A-frags: tile0 = rows 0-15, tile1 = rows 16-31 ----
    const float* z0 = smem + SZ_OFF + wid * 256;
    uint32_t A0g, A0G, A1g, A1G;
    {
        int i0 = g * 8 + 2 * t;
        A0g = pack_f16x2(z0[i0],       z0[i0 + 1]);
        A0G = pack_f16x2(z0[i0 + 64],  z0[i0 + 65]);
        A1g = pack_f16x2(z0[i0 + 128], z0[i0 + 129]);
        A1G = pack_f16x2(z0[i0 + 192], z0[i0 + 193]);
    }

    // ---- loop: this warp's 64 chunk-pairs (half of f) ----
    // GEMM2 accumulates in f16 with 4 rotating accumulator slots per tile (32 steps each,
    // interleaved cp%4), summed in fp32 after the loop.
    uint32_t hacc0[4][2] = {{0,0},{0,0},{0,0},{0,0}};
    uint32_t hacc1[4][2] = {{0,0},{0,0},{0,0},{0,0}};
    const int cpbase = half << 6;

    #pragma unroll 4
    for (int i = 0; i < 64; i++) {
        const int cp = cpbase + i;
        uint4 wq = pWB[(cp << 5) + lane];          // (w1c0, w1c1, w2c0, w2c1)
        uint2 bw = pB16[(cp << 2) + t];            // (bias c0, bias c1) f16x2
        const int s = i & 3;

        uint32_t d00, d01, d10, d11;
        MMA8_H(d00, d01, A0g, A0G, wq.x, bw.x, bw.x);
        MMA8_H(d10, d11, A0g, A0G, wq.y, bw.y, bw.y);
        d00 = hmax2z(d00); d01 = hmax2z(d01); d10 = hmax2z(d10); d11 = hmax2z(d11);
        MMA16_H(hacc0[s][0], hacc0[s][1],
                d00,d01,d10,d11, wq.z,wq.w,
                hacc0[s][0], hacc0[s][1]);

        MMA8_H(d00, d01, A1g, A1G, wq.x, bw.x, bw.x);
        MMA8_H(d10, d11, A1g, A1G, wq.y, bw.y, bw.y);
        d00 = hmax2z(d00); d01 = hmax2z(d01); d10 = hmax2z(d10); d11 = hmax2z(d11);
        MMA16_H(hacc1[s][0], hacc1[s][1],
                d00,d01,d10,d11, wq.z,wq.w,
                hacc1[s][0], hacc1[s][1]);
    }

    // ---- collapse f16 accumulator slots in fp32 ----
    float a0_g0 = 0.f, a0_g1 = 0.f, a0_G0 = 0.f, a0_G1 = 0.f;
    float a1_g0 = 0.f, a1_g1 = 0.f, a1_G0 = 0.f, a1_G1 = 0.f;
    #pragma unroll
    for (int s = 0; s < 4; s++) {
        float2 v;
        v = h2_to_f2(hacc0[s][0]); a0_g0 += v.x; a0_g1 += v.y;
        v = h2_to_f2(hacc0[s][1]); a0_G0 += v.x; a0_G1 += v.y;
        v = h2_to_f2(hacc1[s][0]); a1_g0 += v.x; a1_g1 += v.y;
        v = h2_to_f2(hacc1[s][1]); a1_G0 += v.x; a1_G1 += v.y;
    }

    // ---- exchange partial sums between the two f-halves ----
    __syncthreads();
    float* sE = smem + SZ_OFF + wid * 256;
    sE[(g)*8      + 2*t]     = a0_g0;
    sE[(g)*8      + 2*t + 1] = a0_g1;
    sE[(g+8)*8    + 2*t]     = a0_G0;
    sE[(g+8)*8    + 2*t + 1] = a0_G1;
    sE[(16+g)*8   + 2*t]     = a1_g0;
    sE[(16+g)*8   + 2*t + 1] = a1_g1;
    sE[(24+g)*8   + 2*t]     = a1_G0;
    sE[(24+g)*8   + 2*t + 1] = a1_G1;
    __syncthreads();

    // ---- epilogue (half-0 warps): residual + b2 + LN2 ----
    if (act && half == 0) {
        const float* sOwn = smem + SZ_OFF + wid * 256       + lane * 8;
        const float* sPar = smem + SZ_OFF + (wid ^ 1) * 256 + lane * 8;
        float w[8]; float s2 = 0.f;
        #pragma unroll
        for (int e = 0; e < 8; e++) {
            w[e] = h[e] + sOwn[e] + sPar[e] + __ldg(b2 + e);
            s2 += w[e];
        }
        float m2 = s2 * 0.125f, v2 = 0.f;
        #pragma unroll
        for (int e = 0; e < 8; e++) { float d = w[e] - m2; v2 += d * d; }
        float inv2 = rsqrtf(v2 * 0.125f + 1e-5f);
        float o[8];
        #pragma unroll
        for (int e = 0; e < 8; e++)
            o[e] = (w[e] - m2) * inv2 * __ldg(g2 + e) + __ldg(be2 + e);
        float* op = out + (size_t)tok * 8;
        *(float4*)op       = make_float4(o[0], o[1], o[2], o[3]);
        *(float4*)(op + 4) = make_float4(o[4], o[5], o[6], o[7]);
    }
}

extern "C" void kernel_launch(void* const* d_in, const int* in_sizes, int n_in,
                              void* d_out, int out_size) {
    const float* x      = (const float*)d_in[0];
    const float* theta  = (const float*)d_in[1];
    const float* phi    = (const float*)d_in[2];
    const float* W1     = (const float*)d_in[3];
    const float* b1     = (const float*)d_in[4];
    const float* W2     = (const float*)d_in[5];
    const float* b2     = (const float*)d_in[6];
    const float* gamma1 = (const float*)d_in[7];
    const float* beta1  = (const float*)d_in[8];
    const float* gamma2 = (const float*)d_in[9];
    const float* beta2  = (const float*)d_in[10];
    float* out = (float*)d_out;

    qtb_pack<<<16, 256>>>(W1, b1, W2);
    cudaFuncSetAttribute(qtb_kernel, cudaFuncAttributeMaxDynamicSharedMemorySize, SMEM_BYTES);
    qtb_kernel<<<GRID, TPB, SMEM_BYTES>>>(x, theta, phi, b2,
                                          gamma1, beta1, gamma2, beta2, out);
}

// round 17
// speedup vs baseline: 1.0590x; 1.0221x over previous
#include <cuda_runtime.h>
#include <cuda_fp16.h>
#include <math.h>
#include <stdint.h>

// QuantumTransformerBlock — closed-form quantum ops + fp16 tensor-core FFN, f-split warp pairs.
// R17 = R16 with: f16 GEMM2 accumulators cut to 2 rotating slots/tile (frees 8 regs), and the
// freed budget spent on a software-pipelined LDS prefetch (wq/bw of i+1 loaded before the MMAs
// of i). GEMM1: mma.m16n8k8.f16 (f16 D/C, bias in C, relu = max.f16x2, D feeds GEMM2 A).
// GEMM2: chunk-paired mma.m16n8k16 f16-acc. Pack kernel prebuilds fragment tables.

#define TPB   1024
#define GRID  148
#define NTASKS 2048
#define PAIRS_PER_BLOCK 14     // 148*14 = 2072 >= 2048

// smem layout (floats)
#define WB_OFF   0        // 16384 u32 as uint4[4096]: [128 cp][32 lane] (w1c0,w1c1,w2c0,w2c1)
#define B16_OFF  16384    // 1024 u32 as uint2[512]: [128 cp][4 t] (bias f16x2 c0, c1)
#define SZ_OFF   17408    // 8192 floats: [32 warp][32 tok][8 j]  z, later partial-sum exchange
#define SMEM_FLOATS (SZ_OFF + 32 * 256)
#define SMEM_BYTES (SMEM_FLOATS * 4)       // 102400

__device__ uint4 g_wb[4096];
__device__ uint2 g_b16[512];

__device__ __forceinline__ uint32_t pack_f16x2(float lo, float hi) {
    uint32_t d; asm("cvt.rn.f16x2.f32 %0, %1, %2;" : "=r"(d) : "f"(hi), "f"(lo)); return d;
}
__device__ __forceinline__ uint32_t hmax2z(uint32_t a) {
    uint32_t d; asm("max.f16x2 %0, %1, %2;" : "=r"(d) : "r"(a), "r"(0u)); return d;
}
__device__ __forceinline__ float2 h2_to_f2(uint32_t u) {
    __half2 hh = *reinterpret_cast<__half2*>(&u);
    return __half22float2(hh);
}

#define MMA8_H(D0,D1, A0,A1, B0, C0,C1) \
  asm("mma.sync.aligned.m16n8k8.row.col.f16.f16.f16.f16 " \
      "{%0,%1}, {%2,%3}, {%4}, {%5,%6};" \
      : "=r"(D0),"=r"(D1) : "r"(A0),"r"(A1), "r"(B0), "r"(C0),"r"(C1))

// m16n8k16, f16 in / f16 out (D,C are 2x f16x2)
#define MMA16_H(D0,D1, A0,A1,A2,A3, B0,B1, C0,C1) \
  asm("mma.sync.aligned.m16n8k16.row.col.f16.f16.f16.f16 " \
      "{%0,%1}, {%2,%3,%4,%5}, {%6,%7}, {%8,%9};" \
      : "=r"(D0),"=r"(D1) \
      : "r"(A0),"r"(A1),"r"(A2),"r"(A3), "r"(B0),"r"(B1), "r"(C0),"r"(C1))

// ---------- pack kernel: build fused mma-fragment tables once ----------
__global__ void qtb_pack(const float* __restrict__ W1, const float* __restrict__ b1,
                         const float* __restrict__ W2)
{
    int i = blockIdx.x * 256 + threadIdx.x;        // [0, 4096)
    {
        int cp = i >> 5, lane_ = i & 31;
        int gq = lane_ >> 2, tq = lane_ & 3;
        int c0 = cp * 2, c1 = c0 + 1;
        int f0 = c0 * 8 + gq, f1 = c1 * 8 + gq;
        uint4 v;
        v.x = pack_f16x2(W1[f0 * 8 + 2 * tq], W1[f0 * 8 + 2 * tq + 1]);
        v.y = pack_f16x2(W1[f1 * 8 + 2 * tq], W1[f1 * 8 + 2 * tq + 1]);
        v.z = pack_f16x2(W2[gq * 2048 + c0 * 8 + 2 * tq], W2[gq * 2048 + c0 * 8 + 2 * tq + 1]);
        v.w = pack_f16x2(W2[gq * 2048 + c1 * 8 + 2 * tq], W2[gq * 2048 + c1 * 8 + 2 * tq + 1]);
        g_wb[i] = v;
    }
    if (i < 512) {
        int cp = i >> 2, tq = i & 3;
        int c0 = cp * 2, c1 = c0 + 1;
        uint2 v;
        v.x = pack_f16x2(b1[c0 * 8 + 2 * tq], b1[c0 * 8 + 2 * tq + 1]);
        v.y = pack_f16x2(b1[c1 * 8 + 2 * tq], b1[c1 * 8 + 2 * tq + 1]);
        g_b16[i] = v;
    }
}

// ---------- main kernel ----------
__global__ void __launch_bounds__(TPB, 1) qtb_kernel(
    const float* __restrict__ x, const float* __restrict__ theta, const float* __restrict__ phi,
    const float* __restrict__ b2,
    const float* __restrict__ g1, const float* __restrict__ be1,
    const float* __restrict__ g2, const float* __restrict__ be2,
    float* __restrict__ out)
{
    extern __shared__ float smem[];
    const int tid = threadIdx.x;
    uint4* pWB  = (uint4*)(smem + WB_OFF);
    uint2* pB16 = (uint2*)(smem + B16_OFF);

    // preamble: coalesced copy of prepacked tables (L2-hot)
    #pragma unroll
    for (int k = 0; k < 4; k++) pWB[tid + k * TPB] = g_wb[tid + k * TPB];
    if (tid < 512) pB16[tid] = g_b16[tid];

    const int wid  = tid >> 5, lane = tid & 31;
    const int g    = lane >> 2, t = lane & 3;
    const int pair = wid >> 1, half = wid & 1;

    const int task = blockIdx.x * PAIRS_PER_BLOCK + pair;
    const bool act = (pair < PAIRS_PER_BLOCK) && (task < NTASKS);
    const int taskc = act ? task : 0;
    const int tok  = taskc * 32 + lane;            // one token per lane

    // ---- front: closed-form attn + LN1 + ffn_quantum (fast __cosf) ----
    float h[8];
    {
        float th_[8], cph[8], gg_[8], bb_[8];
        #pragma unroll
        for (int j = 0; j < 8; j++) {
            th_[j] = __ldg(theta + j);
            cph[j] = __cosf(__ldg(phi + j));
            gg_[j] = __ldg(g1 + j);
            bb_[j] = __ldg(be1 + j);
        }
        const float* xp = x + (size_t)tok * 8;
        float4 a4 = __ldg((const float4*)xp);
        float4 b4 = __ldg((const float4*)(xp + 4));
        float xv[8] = {a4.x, a4.y, a4.z, a4.w, b4.x, b4.y, b4.z, b4.w};

        float c_[8];
        #pragma unroll
        for (int j = 0; j < 8; j++) c_[j] = __cosf(xv[j] + th_[j]);
        float attn[8];
        float pr = c_[0];
        #pragma unroll
        for (int j = 1; j < 8; j++) { pr *= c_[j]; attn[j] = pr; }
        float qr = c_[1];
        #pragma unroll
        for (int j = 2; j < 8; j++) qr *= c_[j];
        attn[0] = qr;

        float y[8]; float s = 0.f;
        #pragma unroll
        for (int j = 0; j < 8; j++) { y[j] = xv[j] + attn[j]; s += y[j]; }
        float m = s * 0.125f, v = 0.f;
        #pragma unroll
        for (int j = 0; j < 8; j++) { float d = y[j] - m; v += d * d; }
        float inv = rsqrtf(v * 0.125f + 1e-5f);

        float* sz = smem + SZ_OFF + wid * 256 + lane * 8;
        #pragma unroll
        for (int j = 0; j < 8; j++) {
            h[j] = (y[j] - m) * inv * gg_[j] + bb_[j];
            sz[j] = cph[j] * __cosf(h[j]);         // z (per-warp private copy)
        }
    }
    __syncthreads();                                // tables + z ready

    // ---- A-frags: tile0 = rows 0-15, tile1 = rows 16-31 ----
    const float* z0 = smem + SZ_OFF + wid * 256;
    uint32_t A0g, A0G, A1g, A1G;
    {
        int i0 = g * 8 + 2 * t;
        A0g = pack_f16x2(z0[i0],       z0[i0 + 1]);
        A0G = pack_f16x2(z0[i0 + 64],  z0[i0 + 65]);
        A1g = pack_f16x2(z0[i0 + 128], z0[i0 + 129]);
        A1G = pack_f16x2(z0[i0 + 192], z0[i0 + 193]);
    }

    // ---- loop: this warp's 64 chunk-pairs, prefetch-pipelined ----
    // GEMM2 accumulates in f16 with 2 rotating slots per tile (32 steps each),
    // summed in fp32 after the loop. Prefetch of i+1 hides LDS under the MMAs of i.
    uint32_t hacc0[2][2] = {{0,0},{0,0}};
    uint32_t hacc1[2][2] = {{0,0},{0,0}};
    const int cpbase = half << 6;

    uint4 wq = pWB[(cpbase << 5) + lane];           // prologue load (iter 0)
    uint2 bw = pB16[(cpbase << 2) + t];

    #pragma unroll 4
    for (int i = 0; i < 64; i++) {
        const int cpn = cpbase + i + 1;             // prefetch i+1; one-past-end lands in
        uint4 nwq = pWB[(cpn << 5) + lane];         //  adjacent smem regions, never consumed
        uint2 nbw = pB16[(cpn << 2) + t];
        const int s = i & 1;

        uint32_t d00, d01, d10, d11;
        MMA8_H(d00, d01, A0g, A0G, wq.x, bw.x, bw.x);
        MMA8_H(d10, d11, A0g, A0G, wq.y, bw.y, bw.y);
        d00 = hmax2z(d00); d01 = hmax2z(d01); d10 = hmax2z(d10); d11 = hmax2z(d11);
        MMA16_H(hacc0[s][0], hacc0[s][1],
                d00,d01,d10,d11, wq.z,wq.w,
                hacc0[s][0], hacc0[s][1]);

        MMA8_H(d00, d01, A1g, A1G, wq.x, bw.x, bw.x);
        MMA8_H(d10, d11, A1g, A1G, wq.y, bw.y, bw.y);
        d00 = hmax2z(d00); d01 = hmax2z(d01); d10 = hmax2z(d10); d11 = hmax2z(d11);
        MMA16_H(hacc1[s][0], hacc1[s][1],
                d00,d01,d10,d11, wq.z,wq.w,
                hacc1[s][0], hacc1[s][1]);

        wq = nwq; bw = nbw;
    }

    // ---- collapse f16 accumulator slots in fp32 ----
    float a0_g0 = 0.f, a0_g1 = 0.f, a0_G0 = 0.f, a0_G1 = 0.f;
    float a1_g0 = 0.f, a1_g1 = 0.f, a1_G0 = 0.f, a1_G1 = 0.f;
    #pragma unroll
    for (int s = 0; s < 2; s++) {
        float2 v;
        v = h2_to_f2(hacc0[s][0]); a0_g0 += v.x; a0_g1 += v.y;
        v = h2_to_f2(hacc0[s][1]); a0_G0 += v.x; a0_G1 += v.y;
        v = h2_to_f2(hacc1[s][0]); a1_g0 += v.x; a1_g1 += v.y;
        v = h2_to_f2(hacc1[s][1]); a1_G0 += v.x; a1_G1 += v.y;
    }

    // ---- exchange partial sums between the two f-halves ----
    __syncthreads();
    float* sE = smem + SZ_OFF + wid * 256;
    sE[(g)*8      + 2*t]     = a0_g0;
    sE[(g)*8      + 2*t + 1] = a0_g1;
    sE[(g+8)*8    + 2*t]     = a0_G0;
    sE[(g+8)*8    + 2*t + 1] = a0_G1;
    sE[(16+g)*8   + 2*t]     = a1_g0;
    sE[(16+g)*8   + 2*t + 1] = a1_g1;
    sE[(24+g)*8   + 2*t]     = a1_G0;
    sE[(24+g)*8   + 2*t + 1] = a1_G1;
    __syncthreads();

    // ---- epilogue (half-0 warps): residual + b2 + LN2 ----
    if (act && half == 0) {
        const float* sOwn = smem + SZ_OFF + wid * 256       + lane * 8;
        const float* sPar = smem + SZ_OFF + (wid ^ 1) * 256 + lane * 8;
        float w[8]; float s2 = 0.f;
        #pragma unroll
        for (int e = 0; e < 8; e++) {
            w[e] = h[e] + sOwn[e] + sPar[e] + __ldg(b2 + e);
            s2 += w[e];
        }
        float m2 = s2 * 0.125f, v2 = 0.f;
        #pragma unroll
        for (int e = 0; e < 8; e++) { float d = w[e] - m2; v2 += d * d; }
        float inv2 = rsqrtf(v2 * 0.125f + 1e-5f);
        float o[8];
        #pragma unroll
        for (int e = 0; e < 8; e++)
            o[e] = (w[e] - m2) * inv2 * __ldg(g2 + e) + __ldg(be2 + e);
        float* op = out + (size_t)tok * 8;
        *(float4*)op       = make_float4(o[0], o[1], o[2], o[3]);
        *(float4*)(op + 4) = make_float4(o[4], o[5], o[6], o[7]);
    }
}

extern "C" void kernel_launch(void* const* d_in, const int* in_sizes, int n_in,
                              void* d_out, int out_size) {
    const float* x      = (const float*)d_in[0];
    const float* theta  = (const float*)d_in[1];
    const float* phi    = (const float*)d_in[2];
    const float* W1     = (const float*)d_in[3];
    const float* b1     = (const float*)d_in[4];
    const float* W2     = (const float*)d_in[5];
    const float* b2     = (const float*)d_in[6];
    const float* gamma1 = (const float*)d_in[7];
    const float* beta1  = (const float*)d_in[8];
    const float* gamma2 = (const float*)d_in[9];
    const float* beta2  = (const float*)d_in[10];
    float* out = (float*)d_out;

    qtb_pack<<<16, 256>>>(W1, b1, W2);
    cudaFuncSetAttribute(qtb_kernel, cudaFuncAttributeMaxDynamicSharedMemorySize, SMEM_BYTES);
    qtb_kernel<<<GRID, TPB, SMEM_BYTES>>>(x, theta, phi, b2,
                                          gamma1, beta1, gamma2, beta2, out);
}